// round 8
// baseline (speedup 1.0000x reference)
#include <cuda_runtime.h>
#include <cstdint>

#define NROWS 200000
#define CIN1  64
#define COUT  128
#define NTAPS 27
#define EPSBN 1e-5f
#define STATS_BLOCKS 256

// ---------------- scratch (device globals; no allocation allowed) ----------
__device__ float g_hpre[(size_t)NROWS * COUT];    // conv1 pre-BN
__device__ float g_respre[(size_t)NROWS * COUT];  // conv2 pre-BN
__device__ float g_skippre[(size_t)NROWS * COUT]; // skip pre-BN
__device__ signed char g_fq1[(size_t)NROWS * CIN1];
__device__ signed char g_fq2[(size_t)NROWS * CIN1];
__device__ signed char g_hq1[(size_t)NROWS * COUT];
__device__ signed char g_hq2[(size_t)NROWS * COUT];
__device__ signed char g_w1q1[(size_t)NTAPS * COUT * CIN1];  // [tap][n][k]
__device__ signed char g_w1q2[(size_t)NTAPS * COUT * CIN1];
__device__ signed char g_w2q1[(size_t)NTAPS * COUT * COUT];
__device__ signed char g_w2q2[(size_t)NTAPS * COUT * COUT];
__device__ signed char g_wskq1[(size_t)COUT * CIN1];
__device__ signed char g_wskq2[(size_t)COUT * CIN1];
__device__ float g_part_sum[STATS_BLOCKS][COUT];
__device__ float g_part_sq[STATS_BLOCKS][COUT];
__device__ float g_part_min[STATS_BLOCKS][COUT];
__device__ float g_part_max[STATS_BLOCKS][COUT];
__device__ float g_pmax[256];
__device__ float g_inv[3][COUT];    // g * rsqrt(var+eps)
__device__ float g_shift[3][COUT];  // b - mean*inv
__device__ float g_qscale[8];       // 0=feats 1=h 2=w1 3=w2 4=wsk
__device__ float g_qinv[8];

// ---------------- PTX helpers (baseline features only) -----------------------
__device__ __forceinline__ uint32_t smem_u32(const void* p) {
    uint32_t a;
    asm("{ .reg .u64 t; cvta.to.shared.u64 t, %1; cvt.u32.u64 %0, t; }"
        : "=r"(a) : "l"(p));
    return a;
}
__device__ __forceinline__ void cpasync16(uint32_t dst, const void* src, int srcsize) {
    asm volatile("cp.async.cg.shared.global [%0], [%1], 16, %2;"
                 :: "r"(dst), "l"(src), "r"(srcsize));
}
__device__ __forceinline__ void cpcommit() {
    asm volatile("cp.async.commit_group;");
}
__device__ __forceinline__ void ldm4(uint32_t* r, uint32_t addr) {
    asm volatile("ldmatrix.sync.aligned.m8n8.x4.shared.b16 {%0,%1,%2,%3}, [%4];"
                 : "=r"(r[0]), "=r"(r[1]), "=r"(r[2]), "=r"(r[3]) : "r"(addr));
}
__device__ __forceinline__ void mma_s8(int* d, const uint32_t* a, const uint32_t* b) {
    asm volatile(
        "mma.sync.aligned.m16n8k32.row.col.s32.s8.s8.s32 "
        "{%0,%1,%2,%3},{%4,%5,%6,%7},{%8,%9},{%0,%1,%2,%3};"
        : "+r"(d[0]), "+r"(d[1]), "+r"(d[2]), "+r"(d[3])
        : "r"(a[0]), "r"(a[1]), "r"(a[2]), "r"(a[3]), "r"(b[0]), "r"(b[1]));
}

// smem geometry: rows of 64 s8 padded to 80B -> conflict-free ldmatrix
#define ROWB   80
#define TILE_B (128 * ROWB)          // 10240 B per 128x64 s8 tile
#define STAGE_B (4 * TILE_B)         // Xq1, Xq2, Wq1, Wq2

// ---------------- int8 gathered multi-tap GEMM -------------------------------
// Y[128-tile,128] = s_x*s_w * sum_taps gather(q)[128,K] @ Wq[K,128] digits.
template <bool GATHER>
__global__ __launch_bounds__(512, 1)
void mma_conv_s8(const signed char* __restrict__ Xq1,
                 const signed char* __restrict__ Xq2,
                 const int* __restrict__ nbr,
                 const signed char* __restrict__ Wq1,
                 const signed char* __restrict__ Wq2,
                 const float* __restrict__ sxp, const float* __restrict__ swp,
                 float* __restrict__ Y, int ntaps, int xk) {
    extern __shared__ char smem[];
    const uint32_t sb = smem_u32(smem);
    const int tid = threadIdx.x;
    const int wid = tid >> 5;
    const int lid = tid & 31;
    const int row0 = blockIdx.x * 128;
    const int cpt = xk >> 6;            // 64-wide k-chunks per tap
    const int nsub = ntaps * cpt;

    const int wm = (wid & 3) * 32;      // warp M offset
    const int wn = (wid >> 2) * 32;     // warp N offset

    const int lr = tid >> 2;            // load row 0..127
    const int lc = tid & 3;             // 16B chunk 0..3

    int accA[2][4][4], accC[2][4][4];
#pragma unroll
    for (int i = 0; i < 2; i++)
#pragma unroll
        for (int j = 0; j < 4; j++)
#pragma unroll
            for (int q = 0; q < 4; q++) { accA[i][j][q] = 0; accC[i][j][q] = 0; }

    auto load_stage = [&](int s) {
        const int buf = s & 1;
        const int tap = s / cpt;
        const int kc = s - tap * cpt;
        const uint32_t st = sb + buf * STAGE_B;
        const int grow = row0 + lr;
        int src;
        if (GATHER)
            src = (grow < NROWS) ? __ldg(nbr + (size_t)tap * NROWS + grow) : NROWS;
        else
            src = grow;
        const bool val = (unsigned)src < (unsigned)NROWS;
        const int srow = val ? src : 0;
        const int sz = val ? 16 : 0;
        const uint32_t d = st + lr * ROWB + lc * 16;
        const size_t xo = (size_t)srow * xk + kc * 64 + lc * 16;
        cpasync16(d, Xq1 + xo, sz);
        cpasync16(d + TILE_B, Xq2 + xo, sz);
        const size_t wo = ((size_t)tap * 128 + lr) * xk + kc * 64 + lc * 16;
        cpasync16(d + 2 * TILE_B, Wq1 + wo, 16);
        cpasync16(d + 3 * TILE_B, Wq2 + wo, 16);
    };

    load_stage(0);
    cpcommit();

    const int b_nrow = (lid & 7) + ((lid >> 4) << 3);
    const int b_kof = ((lid >> 3) & 1) * 16;
    const int a_row = lid & 15;
    const int a_kof = (lid >> 4) * 16;

    for (int s = 0; s < nsub; s++) {
        if (s + 1 < nsub) {
            load_stage(s + 1);
            cpcommit();
            asm volatile("cp.async.wait_group 1;");
        } else {
            asm volatile("cp.async.wait_group 0;");
        }
        __syncthreads();

        const uint32_t st = sb + (s & 1) * STAGE_B;
#pragma unroll
        for (int kb = 0; kb < 64; kb += 32) {
            // B fragments: 2 pairs of n8 tiles per digit
            uint32_t b1[4][2], b2[4][2];
#pragma unroll
            for (int p = 0; p < 2; p++) {
                const uint32_t wa =
                    st + 2 * TILE_B + (wn + p * 16 + b_nrow) * ROWB + kb + b_kof;
                uint32_t r[4];
                ldm4(r, wa);
                b1[p * 2][0] = r[0]; b1[p * 2][1] = r[1];
                b1[p * 2 + 1][0] = r[2]; b1[p * 2 + 1][1] = r[3];
                ldm4(r, wa + TILE_B);
                b2[p * 2][0] = r[0]; b2[p * 2][1] = r[1];
                b2[p * 2 + 1][0] = r[2]; b2[p * 2 + 1][1] = r[3];
            }
#pragma unroll
            for (int mi = 0; mi < 2; mi++) {
                uint32_t a1[4], a2[4];
                const uint32_t aa =
                    st + (wm + mi * 16 + a_row) * ROWB + kb + a_kof;
                ldm4(a1, aa);
                ldm4(a2, aa + TILE_B);
#pragma unroll
                for (int ni = 0; ni < 4; ni++) {
                    mma_s8(accA[mi][ni], a1, b1[ni]);
                    mma_s8(accC[mi][ni], a1, b2[ni]);
                    mma_s8(accC[mi][ni], a2, b1[ni]);
                }
            }
        }
        __syncthreads();
    }

    // ---- epilogue: combine digits, scale, write fp32
    const float sxw = __ldg(sxp) * __ldg(swp);
    const float c254 = 1.0f / 254.0f;
#pragma unroll
    for (int mi = 0; mi < 2; mi++) {
        const int m0 = row0 + wm + mi * 16 + (lid >> 2);
#pragma unroll
        for (int ni = 0; ni < 4; ni++) {
            const int col = wn + ni * 8 + 2 * (lid & 3);
            float v0 = sxw * ((float)accA[mi][ni][0] + (float)accC[mi][ni][0] * c254);
            float v1 = sxw * ((float)accA[mi][ni][1] + (float)accC[mi][ni][1] * c254);
            float v2 = sxw * ((float)accA[mi][ni][2] + (float)accC[mi][ni][2] * c254);
            float v3 = sxw * ((float)accA[mi][ni][3] + (float)accC[mi][ni][3] * c254);
            if (m0 < NROWS)
                *(float2*)(Y + (size_t)m0 * 128 + col) = make_float2(v0, v1);
            if (m0 + 8 < NROWS)
                *(float2*)(Y + (size_t)(m0 + 8) * 128 + col) = make_float2(v2, v3);
        }
    }
}

// ---------------- absmax reduction (deterministic) ---------------------------
__global__ void absmax_kernel(const float* __restrict__ X, long long n) {
    __shared__ float sm[256];
    float m = 0.f;
    for (long long i = (long long)blockIdx.x * 256 + threadIdx.x; i < n;
         i += (long long)gridDim.x * 256)
        m = fmaxf(m, fabsf(X[i]));
    sm[threadIdx.x] = m;
    __syncthreads();
    for (int o = 128; o; o >>= 1) {
        if (threadIdx.x < o) sm[threadIdx.x] = fmaxf(sm[threadIdx.x], sm[threadIdx.x + o]);
        __syncthreads();
    }
    if (threadIdx.x == 0) g_pmax[blockIdx.x] = sm[0];
}

__global__ void finalize_max_kernel(int slot) {
    __shared__ float sm[256];
    sm[threadIdx.x] = g_pmax[threadIdx.x];
    __syncthreads();
    for (int o = 128; o; o >>= 1) {
        if (threadIdx.x < o) sm[threadIdx.x] = fmaxf(sm[threadIdx.x], sm[threadIdx.x + o]);
        __syncthreads();
    }
    if (threadIdx.x == 0) {
        float m = sm[0];
        float s = (m > 0.f) ? (m / 127.0f) : 1.0f;
        g_qscale[slot] = s;
        g_qinv[slot] = 1.0f / s;
    }
}

// ---------------- quantize helpers -------------------------------------------
__device__ __forceinline__ void quant2(float v, float qi, signed char& q1, signed char& q2) {
    float y = v * qi;
    int a = __float2int_rn(y);
    int b = __float2int_rn((y - (float)a) * 254.0f);
    q1 = (signed char)a;
    q2 = (signed char)b;
}

__global__ void quantX_kernel(const float4* __restrict__ X,
                              uchar4* __restrict__ q1o, uchar4* __restrict__ q2o,
                              long long n4, int slot) {
    long long i = (long long)blockIdx.x * blockDim.x + threadIdx.x;
    if (i >= n4) return;
    const float qi = g_qinv[slot];
    float4 v = X[i];
    signed char a0, a1, a2, a3, b0, b1, b2, b3;
    quant2(v.x, qi, a0, b0); quant2(v.y, qi, a1, b1);
    quant2(v.z, qi, a2, b2); quant2(v.w, qi, a3, b3);
    q1o[i] = make_uchar4((unsigned char)a0, (unsigned char)a1, (unsigned char)a2, (unsigned char)a3);
    q2o[i] = make_uchar4((unsigned char)b0, (unsigned char)b1, (unsigned char)b2, (unsigned char)b3);
}

// W [tap][k][128] fp32 -> [tap][n][k] s8 digits
__global__ void wquant_kernel(const float* __restrict__ W,
                              signed char* __restrict__ q1o,
                              signed char* __restrict__ q2o,
                              int taps, int K, int slot) {
    int i = blockIdx.x * blockDim.x + threadIdx.x;
    int total = taps * 128 * K;
    if (i >= total) return;
    const float qi = g_qinv[slot];
    int kk = i % K;
    int t2 = i / K;
    int n = t2 & 127;
    int tap = t2 >> 7;
    float v = __ldg(W + ((size_t)tap * K + kk) * 128 + n);
    signed char a, b;
    quant2(v, qi, a, b);
    q1o[i] = a;
    q2o[i] = b;
}

// ---------------- deterministic column stats (+min/max) ----------------------
__global__ void stats_kernel(const float* __restrict__ X) {
    __shared__ float ssum[2][COUT], ssq[2][COUT], smn[2][COUT], smx[2][COUT];
    const int col = threadIdx.x & (COUT - 1);
    const int half = threadIdx.x >> 7;
    float s = 0.f, q = 0.f, mn = 1e30f, mx = -1e30f;
    for (long long r = (long long)blockIdx.x * 2 + half; r < NROWS;
         r += (long long)gridDim.x * 2) {
        float v = X[r * COUT + col];
        s += v; q += v * v;
        mn = fminf(mn, v); mx = fmaxf(mx, v);
    }
    ssum[half][col] = s; ssq[half][col] = q;
    smn[half][col] = mn; smx[half][col] = mx;
    __syncthreads();
    if (half == 0) {
        g_part_sum[blockIdx.x][col] = ssum[0][col] + ssum[1][col];
        g_part_sq[blockIdx.x][col]  = ssq[0][col] + ssq[1][col];
        g_part_min[blockIdx.x][col] = fminf(smn[0][col], smn[1][col]);
        g_part_max[blockIdx.x][col] = fmaxf(smx[0][col], smx[1][col]);
    }
}

__global__ void finalize_kernel(const float* __restrict__ g,
                                const float* __restrict__ b, int slot, int qslot) {
    __shared__ float red[COUT];
    const int col = threadIdx.x;  // 128 threads
    float s = 0.f, q = 0.f, mn = 1e30f, mx = -1e30f;
    for (int i = 0; i < STATS_BLOCKS; i++) {
        s += g_part_sum[i][col];
        q += g_part_sq[i][col];
        mn = fminf(mn, g_part_min[i][col]);
        mx = fmaxf(mx, g_part_max[i][col]);
    }
    float mean = s * (1.0f / NROWS);
    float var = q * (1.0f / NROWS) - mean * mean;
    float inv = g[col] * rsqrtf(var + EPSBN);
    float shift = b[col] - mean * inv;
    g_inv[slot][col] = inv;
    g_shift[slot][col] = shift;
    if (qslot >= 0) {
        red[col] = fmaxf(fabsf(inv * mx + shift), fabsf(inv * mn + shift));
        __syncthreads();
        for (int o = 64; o; o >>= 1) {
            if (col < o) red[col] = fmaxf(red[col], red[col + o]);
            __syncthreads();
        }
        if (col == 0) {
            float m = red[0];
            float sc = (m > 0.f) ? (m / 127.0f) : 1.0f;
            g_qscale[qslot] = sc;
            g_qinv[qslot] = 1.0f / sc;
        }
    }
}

// ---------------- BN apply (slot 0) fused with int8 quant --------------------
__global__ void bnquant_kernel(const float4* __restrict__ X,
                               uchar4* __restrict__ q1o, uchar4* __restrict__ q2o) {
    long long i = (long long)blockIdx.x * blockDim.x + threadIdx.x;
    const long long total = (long long)NROWS * COUT / 4;
    if (i >= total) return;
    int c4 = (int)(i & (COUT / 4 - 1)) * 4;
    const float qi = g_qinv[1];
    float4 v = X[i];
    v.x = v.x * g_inv[0][c4 + 0] + g_shift[0][c4 + 0];
    v.y = v.y * g_inv[0][c4 + 1] + g_shift[0][c4 + 1];
    v.z = v.z * g_inv[0][c4 + 2] + g_shift[0][c4 + 2];
    v.w = v.w * g_inv[0][c4 + 3] + g_shift[0][c4 + 3];
    signed char a0, a1, a2, a3, b0, b1, b2, b3;
    quant2(v.x, qi, a0, b0); quant2(v.y, qi, a1, b1);
    quant2(v.z, qi, a2, b2); quant2(v.w, qi, a3, b3);
    q1o[i] = make_uchar4((unsigned char)a0, (unsigned char)a1, (unsigned char)a2, (unsigned char)a3);
    q2o[i] = make_uchar4((unsigned char)b0, (unsigned char)b1, (unsigned char)b2, (unsigned char)b3);
}

// ---------------- final: relu(bn(res) + bn(skip)) ----------------------------
__global__ void final_kernel(float4* __restrict__ out) {
    long long i = (long long)blockIdx.x * blockDim.x + threadIdx.x;
    const long long total = (long long)NROWS * COUT / 4;
    if (i >= total) return;
    int c4 = (int)(i & (COUT / 4 - 1)) * 4;
    const float4 r = ((const float4*)g_respre)[i];
    const float4 s = ((const float4*)g_skippre)[i];
    float4 o;
    o.x = fmaxf(r.x * g_inv[1][c4 + 0] + g_shift[1][c4 + 0] +
                s.x * g_inv[2][c4 + 0] + g_shift[2][c4 + 0], 0.f);
    o.y = fmaxf(r.y * g_inv[1][c4 + 1] + g_shift[1][c4 + 1] +
                s.y * g_inv[2][c4 + 1] + g_shift[2][c4 + 1], 0.f);
    o.z = fmaxf(r.z * g_inv[1][c4 + 2] + g_shift[1][c4 + 2] +
                s.z * g_inv[2][c4 + 2] + g_shift[2][c4 + 2], 0.f);
    o.w = fmaxf(r.w * g_inv[1][c4 + 3] + g_shift[1][c4 + 3] +
                s.w * g_inv[2][c4 + 3] + g_shift[2][c4 + 3], 0.f);
    out[i] = o;
}

// ---------------- launch ------------------------------------------------------
extern "C" void kernel_launch(void* const* d_in, const int* in_sizes, int n_in,
                              void* d_out, int out_size) {
    const float* feats = (const float*)d_in[0];
    const int*   nbr   = (const int*)d_in[1];
    const float* W1    = (const float*)d_in[2];
    const float* g1    = (const float*)d_in[3];
    const float* b1    = (const float*)d_in[4];
    const float* W2    = (const float*)d_in[5];
    const float* g2    = (const float*)d_in[6];
    const float* b2    = (const float*)d_in[7];
    const float* Wsk   = (const float*)d_in[8];
    const float* gsk   = (const float*)d_in[9];
    const float* bsk   = (const float*)d_in[10];
    float* out = (float*)d_out;

    float *hpre, *respre, *skippre, *qscale;
    signed char *fq1, *fq2, *hq1, *hq2, *w1q1, *w1q2, *w2q1, *w2q2, *wskq1, *wskq2;
    cudaGetSymbolAddress((void**)&hpre, g_hpre);
    cudaGetSymbolAddress((void**)&respre, g_respre);
    cudaGetSymbolAddress((void**)&skippre, g_skippre);
    cudaGetSymbolAddress((void**)&qscale, g_qscale);
    cudaGetSymbolAddress((void**)&fq1, g_fq1);
    cudaGetSymbolAddress((void**)&fq2, g_fq2);
    cudaGetSymbolAddress((void**)&hq1, g_hq1);
    cudaGetSymbolAddress((void**)&hq2, g_hq2);
    cudaGetSymbolAddress((void**)&w1q1, g_w1q1);
    cudaGetSymbolAddress((void**)&w1q2, g_w1q2);
    cudaGetSymbolAddress((void**)&w2q1, g_w2q1);
    cudaGetSymbolAddress((void**)&w2q2, g_w2q2);
    cudaGetSymbolAddress((void**)&wskq1, g_wskq1);
    cudaGetSymbolAddress((void**)&wskq2, g_wskq2);

    const int SMEM_BYTES = 2 * STAGE_B;  // 81920
    cudaFuncSetAttribute(mma_conv_s8<true>,
                         cudaFuncAttributeMaxDynamicSharedMemorySize, SMEM_BYTES);
    cudaFuncSetAttribute(mma_conv_s8<false>,
                         cudaFuncAttributeMaxDynamicSharedMemorySize, SMEM_BYTES);

    const int grid = (NROWS + 127) / 128;  // 1563
    const long long total4 = (long long)NROWS * COUT / 4;
    const int egrid = (int)((total4 + 255) / 256);
    const long long f4 = (long long)NROWS * CIN1 / 4;

    // ---- scales (deterministic two-stage max)
    absmax_kernel<<<256, 256>>>(feats, (long long)NROWS * CIN1);
    finalize_max_kernel<<<1, 256>>>(0);
    absmax_kernel<<<256, 256>>>(W1, (long long)NTAPS * CIN1 * COUT);
    finalize_max_kernel<<<1, 256>>>(2);
    absmax_kernel<<<256, 256>>>(W2, (long long)NTAPS * COUT * COUT);
    finalize_max_kernel<<<1, 256>>>(3);
    absmax_kernel<<<256, 256>>>(Wsk, (long long)CIN1 * COUT);
    finalize_max_kernel<<<1, 256>>>(4);

    // ---- quantize feats + weights
    quantX_kernel<<<(int)((f4 + 255) / 256), 256>>>((const float4*)feats,
                                                    (uchar4*)fq1, (uchar4*)fq2, f4, 0);
    wquant_kernel<<<(NTAPS * 128 * CIN1 + 255) / 256, 256>>>(W1, w1q1, w1q2, NTAPS, CIN1, 2);
    wquant_kernel<<<(NTAPS * 128 * COUT + 255) / 256, 256>>>(W2, w2q1, w2q2, NTAPS, COUT, 3);
    wquant_kernel<<<(128 * CIN1 + 255) / 256, 256>>>(Wsk, wskq1, wskq2, 1, CIN1, 4);

    // ---- skip: feats @ Wsk
    mma_conv_s8<false><<<grid, 512, SMEM_BYTES>>>(fq1, fq2, nullptr, wskq1, wskq2,
                                                  qscale + 0, qscale + 4, skippre, 1, CIN1);
    // ---- conv1: 27 taps, K=64
    mma_conv_s8<true><<<grid, 512, SMEM_BYTES>>>(fq1, fq2, nbr, w1q1, w1q2,
                                                 qscale + 0, qscale + 2, hpre, NTAPS, CIN1);
    // ---- BN1 stats (+ h quant scale) + fused BN-apply+quant
    stats_kernel<<<STATS_BLOCKS, 256>>>(hpre);
    finalize_kernel<<<1, COUT>>>(g1, b1, 0, 1);
    bnquant_kernel<<<egrid, 256>>>((const float4*)hpre, (uchar4*)hq1, (uchar4*)hq2);
    // ---- conv2: 27 taps, K=128
    mma_conv_s8<true><<<grid, 512, SMEM_BYTES>>>(hq1, hq2, nbr, w2q1, w2q2,
                                                 qscale + 1, qscale + 3, respre, NTAPS, COUT);
    // ---- BN2 + BNskip stats
    stats_kernel<<<STATS_BLOCKS, 256>>>(respre);
    finalize_kernel<<<1, COUT>>>(g2, b2, 1, -1);
    stats_kernel<<<STATS_BLOCKS, 256>>>(skippre);
    finalize_kernel<<<1, COUT>>>(gsk, bsk, 2, -1);
    // ---- out = relu(bn(res) + bn(skip))
    final_kernel<<<egrid, 256>>>((float4*)out);
}

// round 9
// speedup vs baseline: 2.7579x; 2.7579x over previous
#include <cuda_runtime.h>
#include <cuda_bf16.h>
#include <cstdint>

#define NROWS 200000
#define CIN1  64
#define COUT  128
#define NTAPS 27
#define EPSBN 1e-5f
#define STATS_BLOCKS 256

// ---------------- scratch (device globals; no allocation allowed) ----------
__device__ float g_hpre[(size_t)NROWS * COUT];    // conv1 pre-BN
__device__ float g_respre[(size_t)NROWS * COUT];  // conv2 pre-BN
__device__ float g_skippre[(size_t)NROWS * COUT]; // skip pre-BN
__device__ __nv_bfloat16 g_fhi[(size_t)NROWS * CIN1];
__device__ __nv_bfloat16 g_flo[(size_t)NROWS * CIN1];
__device__ __nv_bfloat16 g_hhi[(size_t)NROWS * COUT];
__device__ __nv_bfloat16 g_hlo[(size_t)NROWS * COUT];
__device__ __nv_bfloat16 g_w1hi[(size_t)NTAPS * COUT * CIN1];  // [tap][n][k] K-major
__device__ __nv_bfloat16 g_w1lo[(size_t)NTAPS * COUT * CIN1];
__device__ __nv_bfloat16 g_w2hi[(size_t)NTAPS * COUT * COUT];
__device__ __nv_bfloat16 g_w2lo[(size_t)NTAPS * COUT * COUT];
__device__ __nv_bfloat16 g_wskhi[(size_t)COUT * CIN1];
__device__ __nv_bfloat16 g_wsklo[(size_t)COUT * CIN1];
__device__ float g_part_sum[STATS_BLOCKS][COUT];
__device__ float g_part_sq[STATS_BLOCKS][COUT];
__device__ float g_inv[3][COUT];    // g * rsqrt(var+eps)
__device__ float g_shift[3][COUT];  // b - mean*inv

// ---------------- PTX helpers (baseline features only; no 'a'-gated ops) -----
__device__ __forceinline__ uint32_t smem_u32(const void* p) {
    uint32_t a;
    asm("{ .reg .u64 t; cvta.to.shared.u64 t, %1; cvt.u32.u64 %0, t; }"
        : "=r"(a) : "l"(p));
    return a;
}
__device__ __forceinline__ void cpasync16(uint32_t dst, const void* src, int srcsize) {
    asm volatile("cp.async.cg.shared.global [%0], [%1], 16, %2;"
                 :: "r"(dst), "l"(src), "r"(srcsize));
}
__device__ __forceinline__ void cpcommit() {
    asm volatile("cp.async.commit_group;");
}
__device__ __forceinline__ void ldm4(uint32_t* r, uint32_t addr) {
    asm volatile("ldmatrix.sync.aligned.m8n8.x4.shared.b16 {%0,%1,%2,%3}, [%4];"
                 : "=r"(r[0]), "=r"(r[1]), "=r"(r[2]), "=r"(r[3]) : "r"(addr));
}
__device__ __forceinline__ void mma16816(float* d, const uint32_t* a, const uint32_t* b) {
    asm volatile(
        "mma.sync.aligned.m16n8k16.row.col.f32.bf16.bf16.f32 "
        "{%0,%1,%2,%3},{%4,%5,%6,%7},{%8,%9},{%0,%1,%2,%3};"
        : "+f"(d[0]), "+f"(d[1]), "+f"(d[2]), "+f"(d[3])
        : "r"(a[0]), "r"(a[1]), "r"(a[2]), "r"(a[3]), "r"(b[0]), "r"(b[1]));
}

// smem tile geometry: bf16 rows padded to 40 elems (80B) -> ldmatrix conflict-free
#define ROWB   80
#define TILE_B (128 * ROWB)          // 10240 B per 128x32 tile
#define STAGE_B (4 * TILE_B)         // XH, XL, WH, WL
#define XH_OFF 0
#define XL_OFF TILE_B
#define WH_OFF (2 * TILE_B)
#define WL_OFF (3 * TILE_B)

// ---------------- HMMA gathered multi-tap GEMM -------------------------------
// Y[128-tile, 128] = sum_s gather(X)[128,32] @ W[32,128], split-bf16 3 terms.
template <bool GATHER>
__global__ __launch_bounds__(256, 2)
void mma_conv_kernel(const __nv_bfloat16* __restrict__ Xhi,
                     const __nv_bfloat16* __restrict__ Xlo,
                     const int* __restrict__ nbr,
                     const __nv_bfloat16* __restrict__ Whi,
                     const __nv_bfloat16* __restrict__ Wlo,
                     float* __restrict__ Y, int ntaps, int xk, int cptsh) {
    extern __shared__ char smem[];
    const uint32_t sb = smem_u32(smem);
    const int tid = threadIdx.x;
    const int wid = tid >> 5;
    const int lid = tid & 31;
    const int row0 = blockIdx.x * 128;
    const int kmask = (1 << cptsh) - 1;   // k-chunk index mask within a tap
    const int nsub = ntaps << cptsh;

    const int wm = (wid & 1) * 64;      // warp M offset in tile
    const int wn = (wid >> 1) * 32;     // warp N offset in tile

    // ---- per-thread load mapping: row r, two 16B chunks
    const int lr = tid >> 1;            // 0..127
    const int lc = (tid & 1) * 2;       // chunk pair 0/2

    float acc[4][4][4];
#pragma unroll
    for (int i = 0; i < 4; i++)
#pragma unroll
        for (int j = 0; j < 4; j++)
#pragma unroll
            for (int q = 0; q < 4; q++) acc[i][j][q] = 0.f;

    // gather-index prefetch: resolve nbr for a stage well before its cp.asyncs
    auto src_of = [&](int s) -> int {
        const int grow = row0 + lr;
        if (!GATHER) return grow;
        const int tap = s >> cptsh;
        return (grow < NROWS) ? __ldg(nbr + (size_t)tap * NROWS + grow) : NROWS;
    };

    auto load_stage = [&](int s, int src) {
        const int buf = s & 1;
        const int kc = s & kmask;
        const uint32_t st = sb + buf * STAGE_B;
        const bool val = (unsigned)src < (unsigned)NROWS;
        const int srow = val ? src : 0;
        const int sz = val ? 16 : 0;
        const __nv_bfloat16* xh = Xhi + (size_t)srow * xk + kc * 32;
        const __nv_bfloat16* xl = Xlo + (size_t)srow * xk + kc * 32;
        const uint32_t xd = st + lr * ROWB + lc * 16;
#pragma unroll
        for (int c = 0; c < 2; c++) {
            cpasync16(xd + XH_OFF + c * 16, xh + (lc + c) * 8, sz);
            cpasync16(xd + XL_OFF + c * 16, xl + (lc + c) * 8, sz);
        }
        const int tap = s >> cptsh;
        const __nv_bfloat16* wh = Whi + ((size_t)tap * 128 + lr) * xk + kc * 32;
        const __nv_bfloat16* wl = Wlo + ((size_t)tap * 128 + lr) * xk + kc * 32;
#pragma unroll
        for (int c = 0; c < 2; c++) {
            cpasync16(xd + WH_OFF + c * 16, wh + (lc + c) * 8, 16);
            cpasync16(xd + WL_OFF + c * 16, wl + (lc + c) * 8, 16);
        }
    };

    int src_cur = src_of(0);
    load_stage(0, src_cur);
    cpcommit();
    int src_next = (1 < nsub) ? src_of(1) : 0;   // index for stage 1 in flight

    // fragment address components
    const int b_nrow = (lid & 7) + ((lid >> 4) << 3);   // B ldmatrix row
    const int b_kof = ((lid >> 3) & 1) * 16;            // B k-byte offset within k16
    const int a_row = lid & 15;                         // A ldmatrix row
    const int a_kof = (lid >> 4) * 16;                  // A k-byte offset

    for (int s = 0; s < nsub; s++) {
        // prefetch gather index two stages ahead (LDG latency hidden by compute)
        const int src_fut = (s + 2 < nsub) ? src_of(s + 2) : 0;
        if (s + 1 < nsub) {
            load_stage(s + 1, src_next);
            cpcommit();
            asm volatile("cp.async.wait_group 1;");
        } else {
            asm volatile("cp.async.wait_group 0;");
        }
        __syncthreads();

        const uint32_t st = sb + (s & 1) * STAGE_B;
#pragma unroll
        for (int kh = 0; kh < 2; kh++) {
            const int kb = kh * 32;   // 16 bf16 = 32B
            uint32_t bh[4][2], bl[4][2];
#pragma unroll
            for (int half = 0; half < 2; half++) {
                const uint32_t wa =
                    st + WH_OFF + (wn + half * 16 + b_nrow) * ROWB + kb + b_kof;
                uint32_t r[4];
                ldm4(r, wa);
                bh[half * 2][0] = r[0]; bh[half * 2][1] = r[1];
                bh[half * 2 + 1][0] = r[2]; bh[half * 2 + 1][1] = r[3];
                ldm4(r, wa + (WL_OFF - WH_OFF));
                bl[half * 2][0] = r[0]; bl[half * 2][1] = r[1];
                bl[half * 2 + 1][0] = r[2]; bl[half * 2 + 1][1] = r[3];
            }
#pragma unroll
            for (int mi = 0; mi < 4; mi++) {
                uint32_t ah[4], al[4];
                const uint32_t aa =
                    st + XH_OFF + (wm + mi * 16 + a_row) * ROWB + kb + a_kof;
                ldm4(ah, aa);
                ldm4(al, aa + (XL_OFF - XH_OFF));
#pragma unroll
                for (int ni = 0; ni < 4; ni++) {
                    mma16816(acc[mi][ni], ah, bh[ni]);
                    mma16816(acc[mi][ni], ah, bl[ni]);
                    mma16816(acc[mi][ni], al, bh[ni]);
                }
            }
        }
        __syncthreads();
        src_next = src_fut;
    }

    // ---- epilogue: write fp32
#pragma unroll
    for (int mi = 0; mi < 4; mi++) {
        const int m0 = row0 + wm + mi * 16 + (lid >> 2);
#pragma unroll
        for (int ni = 0; ni < 4; ni++) {
            const int col = wn + ni * 8 + 2 * (lid & 3);
            if (m0 < NROWS)
                *(float2*)(Y + (size_t)m0 * 128 + col) =
                    make_float2(acc[mi][ni][0], acc[mi][ni][1]);
            if (m0 + 8 < NROWS)
                *(float2*)(Y + (size_t)(m0 + 8) * 128 + col) =
                    make_float2(acc[mi][ni][2], acc[mi][ni][3]);
        }
    }
}

// ---------------- prep: W transpose + bf16 split -----------------------------
__global__ void wsplit_kernel(const float* __restrict__ W,
                              __nv_bfloat16* __restrict__ hi,
                              __nv_bfloat16* __restrict__ lo, int taps, int K) {
    int i = blockIdx.x * blockDim.x + threadIdx.x;
    int total = taps * 128 * K;
    if (i >= total) return;
    int kk = i % K;
    int t2 = i / K;
    int n = t2 & 127;
    int tap = t2 >> 7;
    float v = __ldg(W + ((size_t)tap * K + kk) * 128 + n);
    __nv_bfloat16 h = __float2bfloat16(v);
    hi[i] = h;
    lo[i] = __float2bfloat16(v - __bfloat162float(h));
}

// ---------------- prep: feats bf16 split (vector) ----------------------------
__global__ void xsplit_kernel(const float4* __restrict__ X,
                              uint2* __restrict__ hi, uint2* __restrict__ lo,
                              long long n4) {
    long long i = (long long)blockIdx.x * blockDim.x + threadIdx.x;
    if (i >= n4) return;
    float4 v = X[i];
    __nv_bfloat16 hx = __float2bfloat16(v.x), hy = __float2bfloat16(v.y);
    __nv_bfloat16 hz = __float2bfloat16(v.z), hw = __float2bfloat16(v.w);
    __nv_bfloat162 h01, h23, l01, l23;
    h01.x = hx; h01.y = hy; h23.x = hz; h23.y = hw;
    l01.x = __float2bfloat16(v.x - __bfloat162float(hx));
    l01.y = __float2bfloat16(v.y - __bfloat162float(hy));
    l23.x = __float2bfloat16(v.z - __bfloat162float(hz));
    l23.y = __float2bfloat16(v.w - __bfloat162float(hw));
    hi[i] = make_uint2(*(uint32_t*)&h01, *(uint32_t*)&h23);
    lo[i] = make_uint2(*(uint32_t*)&l01, *(uint32_t*)&l23);
}

// ---------------- deterministic column stats --------------------------------
__global__ void stats_kernel(const float* __restrict__ X) {
    __shared__ float ssum[2][COUT];
    __shared__ float ssq[2][COUT];
    const int col = threadIdx.x & (COUT - 1);
    const int half = threadIdx.x >> 7;
    float s = 0.f, q = 0.f;
    for (long long r = (long long)blockIdx.x * 2 + half; r < NROWS;
         r += (long long)gridDim.x * 2) {
        float v = X[r * COUT + col];
        s += v;
        q += v * v;
    }
    ssum[half][col] = s;
    ssq[half][col] = q;
    __syncthreads();
    if (half == 0) {
        g_part_sum[blockIdx.x][col] = ssum[0][col] + ssum[1][col];
        g_part_sq[blockIdx.x][col]  = ssq[0][col] + ssq[1][col];
    }
}

__global__ void finalize_kernel(const float* __restrict__ g,
                                const float* __restrict__ b, int slot) {
    const int col = threadIdx.x;  // 128 threads
    float s = 0.f, q = 0.f;
    for (int i = 0; i < STATS_BLOCKS; i++) {
        s += g_part_sum[i][col];
        q += g_part_sq[i][col];
    }
    float mean = s * (1.0f / NROWS);
    float var = q * (1.0f / NROWS) - mean * mean;
    float inv = g[col] * rsqrtf(var + EPSBN);
    g_inv[slot][col] = inv;
    g_shift[slot][col] = b[col] - mean * inv;
}

// ---------------- BN apply (slot 0) fused with bf16 split --------------------
__global__ void bnsplit_kernel(const float4* __restrict__ X,
                               uint2* __restrict__ hi, uint2* __restrict__ lo) {
    long long i = (long long)blockIdx.x * blockDim.x + threadIdx.x;
    const long long total = (long long)NROWS * COUT / 4;
    if (i >= total) return;
    int c4 = (int)(i & (COUT / 4 - 1)) * 4;
    float4 v = X[i];
    v.x = v.x * g_inv[0][c4 + 0] + g_shift[0][c4 + 0];
    v.y = v.y * g_inv[0][c4 + 1] + g_shift[0][c4 + 1];
    v.z = v.z * g_inv[0][c4 + 2] + g_shift[0][c4 + 2];
    v.w = v.w * g_inv[0][c4 + 3] + g_shift[0][c4 + 3];
    __nv_bfloat16 hx = __float2bfloat16(v.x), hy = __float2bfloat16(v.y);
    __nv_bfloat16 hz = __float2bfloat16(v.z), hw = __float2bfloat16(v.w);
    __nv_bfloat162 h01, h23, l01, l23;
    h01.x = hx; h01.y = hy; h23.x = hz; h23.y = hw;
    l01.x = __float2bfloat16(v.x - __bfloat162float(hx));
    l01.y = __float2bfloat16(v.y - __bfloat162float(hy));
    l23.x = __float2bfloat16(v.z - __bfloat162float(hz));
    l23.y = __float2bfloat16(v.w - __bfloat162float(hw));
    hi[i] = make_uint2(*(uint32_t*)&h01, *(uint32_t*)&h23);
    lo[i] = make_uint2(*(uint32_t*)&l01, *(uint32_t*)&l23);
}

// ---------------- final: relu(bn(res) + bn(skip)) ----------------------------
__global__ void final_kernel(float4* __restrict__ out) {
    long long i = (long long)blockIdx.x * blockDim.x + threadIdx.x;
    const long long total = (long long)NROWS * COUT / 4;
    if (i >= total) return;
    int c4 = (int)(i & (COUT / 4 - 1)) * 4;
    const float4 r = ((const float4*)g_respre)[i];
    const float4 s = ((const float4*)g_skippre)[i];
    float4 o;
    o.x = fmaxf(r.x * g_inv[1][c4 + 0] + g_shift[1][c4 + 0] +
                s.x * g_inv[2][c4 + 0] + g_shift[2][c4 + 0], 0.f);
    o.y = fmaxf(r.y * g_inv[1][c4 + 1] + g_shift[1][c4 + 1] +
                s.y * g_inv[2][c4 + 1] + g_shift[2][c4 + 1], 0.f);
    o.z = fmaxf(r.z * g_inv[1][c4 + 2] + g_shift[1][c4 + 2] +
                s.z * g_inv[2][c4 + 2] + g_shift[2][c4 + 2], 0.f);
    o.w = fmaxf(r.w * g_inv[1][c4 + 3] + g_shift[1][c4 + 3] +
                s.w * g_inv[2][c4 + 3] + g_shift[2][c4 + 3], 0.f);
    out[i] = o;
}

// ---------------- launch ------------------------------------------------------
extern "C" void kernel_launch(void* const* d_in, const int* in_sizes, int n_in,
                              void* d_out, int out_size) {
    const float* feats = (const float*)d_in[0];
    const int*   nbr   = (const int*)d_in[1];
    const float* W1    = (const float*)d_in[2];
    const float* g1    = (const float*)d_in[3];
    const float* b1    = (const float*)d_in[4];
    const float* W2    = (const float*)d_in[5];
    const float* g2    = (const float*)d_in[6];
    const float* b2    = (const float*)d_in[7];
    const float* Wsk   = (const float*)d_in[8];
    const float* gsk   = (const float*)d_in[9];
    const float* bsk   = (const float*)d_in[10];
    float* out = (float*)d_out;

    float *hpre, *respre, *skippre;
    __nv_bfloat16 *fhi, *flo, *hhi, *hlo, *w1hi, *w1lo, *w2hi, *w2lo, *wskhi, *wsklo;
    cudaGetSymbolAddress((void**)&hpre, g_hpre);
    cudaGetSymbolAddress((void**)&respre, g_respre);
    cudaGetSymbolAddress((void**)&skippre, g_skippre);
    cudaGetSymbolAddress((void**)&fhi, g_fhi);
    cudaGetSymbolAddress((void**)&flo, g_flo);
    cudaGetSymbolAddress((void**)&hhi, g_hhi);
    cudaGetSymbolAddress((void**)&hlo, g_hlo);
    cudaGetSymbolAddress((void**)&w1hi, g_w1hi);
    cudaGetSymbolAddress((void**)&w1lo, g_w1lo);
    cudaGetSymbolAddress((void**)&w2hi, g_w2hi);
    cudaGetSymbolAddress((void**)&w2lo, g_w2lo);
    cudaGetSymbolAddress((void**)&wskhi, g_wskhi);
    cudaGetSymbolAddress((void**)&wsklo, g_wsklo);

    const int SMEM_BYTES = 2 * STAGE_B;  // 81920
    cudaFuncSetAttribute(mma_conv_kernel<true>,
                         cudaFuncAttributeMaxDynamicSharedMemorySize, SMEM_BYTES);
    cudaFuncSetAttribute(mma_conv_kernel<false>,
                         cudaFuncAttributeMaxDynamicSharedMemorySize, SMEM_BYTES);

    const int grid = (NROWS + 127) / 128;  // 1563
    const long long total4 = (long long)NROWS * COUT / 4;
    const int egrid = (int)((total4 + 255) / 256);
    const long long f4 = (long long)NROWS * CIN1 / 4;

    // ---- prep (ordered so launch index 3 == conv1, which ncu captures)
    wsplit_kernel<<<(NTAPS * 128 * CIN1 + 255) / 256, 256>>>(W1, w1hi, w1lo, NTAPS, CIN1);
    xsplit_kernel<<<(int)((f4 + 255) / 256), 256>>>((const float4*)feats,
                                                    (uint2*)fhi, (uint2*)flo, f4);
    wsplit_kernel<<<(NTAPS * 128 * COUT + 255) / 256, 256>>>(W2, w2hi, w2lo, NTAPS, COUT);

    // ---- conv1: 27 taps, K=64  (launch index 3 -> profiled)
    mma_conv_kernel<true><<<grid, 256, SMEM_BYTES>>>(fhi, flo, nbr,
                                                     w1hi, w1lo, hpre, NTAPS, CIN1, 1);

    // ---- skip branch
    wsplit_kernel<<<(128 * CIN1 + 255) / 256, 256>>>(Wsk, wskhi, wsklo, 1, CIN1);
    mma_conv_kernel<false><<<grid, 256, SMEM_BYTES>>>(fhi, flo, nullptr,
                                                      wskhi, wsklo, skippre, 1, CIN1, 1);

    // ---- BN1 stats + fused apply+split
    stats_kernel<<<STATS_BLOCKS, 256>>>(hpre);
    finalize_kernel<<<1, COUT>>>(g1, b1, 0);
    bnsplit_kernel<<<egrid, 256>>>((const float4*)hpre, (uint2*)hhi, (uint2*)hlo);
    // ---- conv2: 27 taps, K=128
    mma_conv_kernel<true><<<grid, 256, SMEM_BYTES>>>(hhi, hlo, nbr,
                                                     w2hi, w2lo, respre, NTAPS, COUT, 2);
    // ---- BN2 + BNskip stats
    stats_kernel<<<STATS_BLOCKS, 256>>>(respre);
    finalize_kernel<<<1, COUT>>>(g2, b2, 1);
    stats_kernel<<<STATS_BLOCKS, 256>>>(skippre);
    finalize_kernel<<<1, COUT>>>(gsk, bsk, 2);
    // ---- out = relu(bn(res) + bn(skip))
    final_kernel<<<egrid, 256>>>((float4*)out);
}